// round 3
// baseline (speedup 1.0000x reference)
#include <cuda_runtime.h>
#include <cuda_bf16.h>
#include <cstdint>

// ---------------- problem constants ----------------
#define HW    112
#define IMG   (HW*HW)          // 12544
#define NB    32
#define CIN   128
#define COUT  256
#define NPOS  (NB*IMG)         // 401408
#define KHALF 1152             // 3*3*128
#define KTOT  2304             // [121w ; w] doubled K

// ---------------- scratch ----------------
__device__ int8_t g_xh[(size_t)NPOS * CIN];              // high part  (pairs with 121*sign)
__device__ int8_t g_xl[(size_t)NPOS * CIN];              // low  part  (pairs with sign)
__device__ int8_t g_wq[(size_t)COUT * KTOT];             // [co][part*1152 + tap*128 + c]

// ---------------- helpers (sm_80-level base ISA) ----------------
__device__ __forceinline__ uint32_t smem_to_u32(const void* p) {
    uint32_t a;
    asm("{ .reg .u64 t; cvta.to.shared.u64 t, %1; cvt.u32.u64 %0, t; }" : "=r"(a) : "l"(p));
    return a;
}

__device__ __forceinline__ void cp16(uint32_t dst, const void* src, bool pred) {
    int sz = pred ? 16 : 0;     // src-size 0 -> 16B zfill
    asm volatile("cp.async.cg.shared.global [%0], [%1], 16, %2;"
                 :: "r"(dst), "l"(src), "r"(sz) : "memory");
}

#define CP_COMMIT() asm volatile("cp.async.commit_group;" ::: "memory")
#define CP_WAIT2()  asm volatile("cp.async.wait_group 2;" ::: "memory")

__device__ __forceinline__ void ldsm4(uint32_t* r, uint32_t addr) {
    asm volatile("ldmatrix.sync.aligned.m8n8.x4.shared.b16 {%0,%1,%2,%3}, [%4];"
                 : "=r"(r[0]), "=r"(r[1]), "=r"(r[2]), "=r"(r[3]) : "r"(addr));
}

__device__ __forceinline__ void mma_s8(int* c, const uint32_t* a,
                                       uint32_t b0, uint32_t b1) {
    asm volatile(
        "mma.sync.aligned.m16n8k32.row.col.s32.s8.s8.s32 "
        "{%0,%1,%2,%3}, {%4,%5,%6,%7}, {%8,%9}, {%0,%1,%2,%3};"
        : "+r"(c[0]), "+r"(c[1]), "+r"(c[2]), "+r"(c[3])
        : "r"(a[0]), "r"(a[1]), "r"(a[2]), "r"(a[3]), "r"(b0), "r"(b1));
}

// ---------------- SMEM layout ----------------
// 4 stages. stage s at s*49152: A0 16KB | A1 16KB | B 16KB
// rows = 128 bytes (128 int8 channels), XOR swizzle on 16B units (u ^ (row&7))
static constexpr int BUF_BYTES = 49152;
static constexpr int A_SUB     = 16384;
static constexpr int B_OFF     = 32768;
static constexpr int DYN_SMEM  = 4 * BUF_BYTES;   // 196608

// ---------------- prep kernels ----------------
__global__ void binarize_kernel(const float* __restrict__ w) {
    int i = blockIdx.x * blockDim.x + threadIdx.x;
    if (i >= COUT * KHALF) return;
    int k  = i >> 8;          // HWIO: co fastest
    int co = i & 255;
    float v = w[i];
    int s = (v > 0.f) ? 1 : ((v < 0.f) ? -1 : 0);
    g_wq[co * KTOT + k]         = (int8_t)(121 * s);   // part 0: pairs with h
    g_wq[co * KTOT + KHALF + k] = (int8_t)s;           // part 1: pairs with l
}

__global__ void quant_kernel(const float4* __restrict__ x) {
    int i = blockIdx.x * blockDim.x + threadIdx.x;
    if (i >= (NPOS * CIN) / 4) return;
    float4 v = x[i];
    int q0 = __float2int_rn(fminf(fmaxf(v.x, -7.5f), 7.5f) * 2048.f);
    int q1 = __float2int_rn(fminf(fmaxf(v.y, -7.5f), 7.5f) * 2048.f);
    int q2 = __float2int_rn(fminf(fmaxf(v.z, -7.5f), 7.5f) * 2048.f);
    int q3 = __float2int_rn(fminf(fmaxf(v.w, -7.5f), 7.5f) * 2048.f);
    int h0 = __float2int_rn((float)q0 * (1.f / 121.f));
    int h1 = __float2int_rn((float)q1 * (1.f / 121.f));
    int h2 = __float2int_rn((float)q2 * (1.f / 121.f));
    int h3 = __float2int_rn((float)q3 * (1.f / 121.f));
    int l0 = q0 - 121 * h0, l1 = q1 - 121 * h1;
    int l2 = q2 - 121 * h2, l3 = q3 - 121 * h3;
    uint32_t hp = (uint32_t)(h0 & 255) | ((uint32_t)(h1 & 255) << 8) |
                  ((uint32_t)(h2 & 255) << 16) | ((uint32_t)(h3 & 255) << 24);
    uint32_t lp = (uint32_t)(l0 & 255) | ((uint32_t)(l1 & 255) << 8) |
                  ((uint32_t)(l2 & 255) << 16) | ((uint32_t)(l3 & 255) << 24);
    ((uint32_t*)g_xh)[i] = hp;
    ((uint32_t*)g_xl)[i] = lp;
}

// ---------------- main implicit-GEMM conv (s8 IMMA) ----------------
// One launch per nt (output-channel half). CTA tile: M=256 x N=128.
// 16 warps, warp tile 64x32. 18 K-chunks: 9 taps x {hi-part, lo-part},
// each chunk = 128 int8 of K. 4-stage cp.async pipeline, 1 barrier/chunk.
__global__ __launch_bounds__(512, 1)
void conv_kernel(float* __restrict__ out, int nt) {
    extern __shared__ char smem[];
    const uint32_t smem_u = smem_to_u32(smem);
    const int tid  = threadIdx.x;
    const int wid  = tid >> 5;
    const int lane = tid & 31;
    const int mt   = blockIdx.x;

    // ---- per-thread load slots (fixed across K loop) ----
    // A: 4 slots (2048 x 16B / 512 thr)
    int cbase[4], hh[4], ww[4];
    uint32_t dstA[4];
#pragma unroll
    for (int j = 0; j < 4; ++j) {
        int s = tid + j * 512;
        int t = s >> 10;            // subtile 0/1
        int r = (s >> 3) & 127;     // row in subtile
        int u = s & 7;              // 16B unit
        int p = mt * 256 + t * 128 + r;
        int n = p / IMG;
        int rem = p - n * IMG;
        int h = rem / HW;
        int w = rem - h * HW;
        hh[j] = h; ww[j] = w;
        cbase[j] = ((n * HW + h) * HW + w) * CIN + u * 16;   // bytes (int8)
        dstA[j]  = t * A_SUB + r * 128 + ((u ^ (r & 7)) << 4);
    }
    // B: 2 slots (1024 x 16B / 512 thr)
    int bsrc[2];
    uint32_t dstB[2];
#pragma unroll
    for (int j = 0; j < 2; ++j) {
        int s = tid + j * 512;
        int r = s >> 3;
        int u = s & 7;
        bsrc[j] = (nt * 128 + r) * KTOT + u * 16;            // bytes
        dstB[j] = B_OFF + r * 128 + ((u ^ (r & 7)) << 4);
    }

    // ---- warp tiling ----
    const int wm = (wid & 3) * 64;
    const int wn = (wid >> 2) * 32;
    const int at = wm >> 7;
    const int am = wm & 127;

    int acc[4][4][4];
#pragma unroll
    for (int i = 0; i < 4; ++i)
#pragma unroll
        for (int j = 0; j < 4; ++j)
#pragma unroll
            for (int q = 0; q < 4; ++q) acc[i][j][q] = 0;

    auto issue_loads = [&](int it, int buf) {
        int tap  = it >> 1;
        int part = it & 1;
        int kh = tap / 3, kw = tap - kh * 3;
        const int8_t* __restrict__ xsrc = part ? g_xl : g_xh;
        const int doff = ((kh - 1) * HW + (kw - 1)) * CIN;   // byte shift
        const uint32_t bb = smem_u + buf * BUF_BYTES;
#pragma unroll
        for (int j = 0; j < 4; ++j) {
            unsigned h2 = (unsigned)(hh[j] + kh - 1);
            unsigned w2 = (unsigned)(ww[j] + kw - 1);
            bool ok = (h2 < (unsigned)HW) && (w2 < (unsigned)HW);
            cp16(bb + dstA[j], xsrc + cbase[j] + doff, ok);
        }
        const int woff = part * KHALF + tap * CIN;           // byte offset in B row
#pragma unroll
        for (int j = 0; j < 2; ++j)
            cp16(bb + dstB[j], g_wq + bsrc[j] + woff, true);
    };

    issue_loads(0, 0); CP_COMMIT();
    issue_loads(1, 1); CP_COMMIT();
    issue_loads(2, 2); CP_COMMIT();

    for (int it = 0; it < 18; ++it) {
        CP_WAIT2();                 // chunk `it` resident
        __syncthreads();            // all warps see it; buffer (it-1)%4 free
        if (it + 3 < 18) issue_loads(it + 3, (it + 3) & 3);
        CP_COMMIT();

        const uint32_t bb    = smem_u + (it & 3) * BUF_BYTES;
        const uint32_t Abase = bb + at * A_SUB;
        const uint32_t Bbase = bb + B_OFF;
        const int arow = am + (lane & 15);
        const int brow = wn + (lane & 15);
        const int khi  = (lane >> 4) << 4;   // byte half select

#pragma unroll
        for (int ks = 0; ks < 4; ++ks) {
            const int kb = ks * 32 + khi;    // byte col (k32 per step)
            uint32_t a[4][4];
#pragma unroll
            for (int mf = 0; mf < 4; ++mf) {
                int row = arow + mf * 16;
                uint32_t off = (uint32_t)(row * 128 + kb) ^ (uint32_t)((row & 7) << 4);
                ldsm4(a[mf], Abase + off);
            }
            uint32_t b[2][4];
#pragma unroll
            for (int q = 0; q < 2; ++q) {
                int row = brow + q * 16;
                uint32_t off = (uint32_t)(row * 128 + kb) ^ (uint32_t)((row & 7) << 4);
                ldsm4(b[q], Bbase + off);
            }
#pragma unroll
            for (int mf = 0; mf < 4; ++mf)
#pragma unroll
                for (int nb = 0; nb < 4; ++nb) {
                    int q = nb >> 1, jj = nb & 1;
                    mma_s8(acc[mf][nb], a[mf], b[q][jj], b[q][jj + 2]);
                }
        }
    }

    // ---- epilogue: s32 -> f32 scale -> gmem ----
    const float sc = 1.f / 2048.f;
    const int r0 = lane >> 2;
    const int c0 = (lane & 3) * 2;
#pragma unroll
    for (int mf = 0; mf < 4; ++mf) {
        int m = mt * 256 + wm + mf * 16 + r0;
#pragma unroll
        for (int nb = 0; nb < 4; ++nb) {
            int co = nt * 128 + wn + nb * 8 + c0;
            float* p0 = out + (size_t)m * COUT + co;
            float* p1 = out + (size_t)(m + 8) * COUT + co;
            *(float2*)p0 = make_float2((float)acc[mf][nb][0] * sc,
                                       (float)acc[mf][nb][1] * sc);
            *(float2*)p1 = make_float2((float)acc[mf][nb][2] * sc,
                                       (float)acc[mf][nb][3] * sc);
        }
    }
}

// ---------------- launch ----------------
extern "C" void kernel_launch(void* const* d_in, const int* in_sizes, int n_in,
                              void* d_out, int out_size) {
    const float* x = (const float*)d_in[0];
    const float* w = (const float*)d_in[1];
    float* out = (float*)d_out;

    cudaFuncSetAttribute(conv_kernel,
                         cudaFuncAttributeMaxDynamicSharedMemorySize, DYN_SMEM);

    binarize_kernel<<<(COUT * KHALF + 255) / 256, 256>>>(w);
    quant_kernel<<<(NPOS * CIN / 4 + 255) / 256, 256>>>((const float4*)x);
    conv_kernel<<<NPOS / 256, 512, DYN_SMEM>>>(out, 0);
    conv_kernel<<<NPOS / 256, 512, DYN_SMEM>>>(out, 1);
}

// round 6
// speedup vs baseline: 4.4178x; 4.4178x over previous
#include <cuda_runtime.h>
#include <cuda_fp16.h>
#include <cstdint>

// ---------------- problem constants ----------------
#define HW    112
#define IMG   (HW*HW)          // 12544
#define NB    32
#define CIN   128
#define COUT  256
#define NPOS  (NB*IMG)         // 401408
#define KTOT  1152             // 3*3*128

// ---------------- scratch ( __device__ globals ) ----------------
__device__ __half g_xq[(size_t)NPOS * CIN];           // fp16 copy of x
__device__ __half g_wbin[(size_t)COUT * KTOT];        // sign(w) in fp16, [co][tap*128+c]

// ---------------- helpers (sm_80-level base ISA) ----------------
__device__ __forceinline__ uint32_t smem_to_u32(const void* p) {
    uint32_t a;
    asm("{ .reg .u64 t; cvta.to.shared.u64 t, %1; cvt.u32.u64 %0, t; }" : "=r"(a) : "l"(p));
    return a;
}

__device__ __forceinline__ void cp16(uint32_t dst, const void* src, bool pred) {
    int sz = pred ? 16 : 0;     // src-size 0 -> 16B zfill
    asm volatile("cp.async.cg.shared.global [%0], [%1], 16, %2;"
                 :: "r"(dst), "l"(src), "r"(sz) : "memory");
}

#define CP_COMMIT() asm volatile("cp.async.commit_group;" ::: "memory")
#define CP_WAIT2()  asm volatile("cp.async.wait_group 2;" ::: "memory")

__device__ __forceinline__ void ldsm4(uint32_t* r, uint32_t addr) {
    asm volatile("ldmatrix.sync.aligned.m8n8.x4.shared.b16 {%0,%1,%2,%3}, [%4];"
                 : "=r"(r[0]), "=r"(r[1]), "=r"(r[2]), "=r"(r[3]) : "r"(addr));
}

__device__ __forceinline__ void mma_f16(float* c, const uint32_t* a,
                                        uint32_t b0, uint32_t b1) {
    asm volatile(
        "mma.sync.aligned.m16n8k16.row.col.f32.f16.f16.f32 "
        "{%0,%1,%2,%3}, {%4,%5,%6,%7}, {%8,%9}, {%0,%1,%2,%3};"
        : "+f"(c[0]), "+f"(c[1]), "+f"(c[2]), "+f"(c[3])
        : "r"(a[0]), "r"(a[1]), "r"(a[2]), "r"(a[3]), "r"(b0), "r"(b1));
}

// ---------------- SMEM layout ----------------
// 4 stages. stage s at s*49152: A0 16KB | A1 16KB | B 16KB
// rows = 128 bytes (64 fp16), XOR swizzle on 16B units (u ^ (row&7))
static constexpr int BUF_BYTES = 49152;
static constexpr int A_SUB     = 16384;
static constexpr int B_OFF     = 32768;
static constexpr int DYN_SMEM  = 4 * BUF_BYTES;   // 196608

// ---------------- prep kernels ----------------
__global__ void binarize_kernel(const float* __restrict__ w) {
    int i = blockIdx.x * blockDim.x + threadIdx.x;
    if (i >= COUT * KTOT) return;
    int k  = i >> 8;          // HWIO: co fastest
    int co = i & 255;
    float v = w[i];
    float s = (v > 0.f) ? 1.f : ((v < 0.f) ? -1.f : 0.f);
    g_wbin[co * KTOT + k] = __float2half_rn(s);
}

__global__ void quant_kernel(const float4* __restrict__ x) {
    int i = blockIdx.x * blockDim.x + threadIdx.x;
    if (i >= (NPOS * CIN) / 4) return;
    float4 v = x[i];
    __half2 p0 = make_half2(__float2half_rn(v.x), __float2half_rn(v.y));
    __half2 p1 = make_half2(__float2half_rn(v.z), __float2half_rn(v.w));
    uint2 pk;
    pk.x = *(uint32_t*)&p0;
    pk.y = *(uint32_t*)&p1;
    ((uint2*)g_xq)[i] = pk;
}

// ---------------- main implicit-GEMM conv (fp16 HMMA, single pass) ----------------
// Grid (NPOS/256, 2). CTA tile M=256 x N=128. 16 warps, warp tile 64x32.
// 18 K-chunks: 9 taps x 2 channel-halves, chunk = K=64 fp16 (128B rows).
// 4-stage cp.async pipeline, one __syncthreads per chunk.
__global__ __launch_bounds__(512, 1)
void conv_kernel(float* __restrict__ out) {
    extern __shared__ char smem[];
    const uint32_t smem_u = smem_to_u32(smem);
    const int tid  = threadIdx.x;
    const int wid  = tid >> 5;
    const int lane = tid & 31;
    const int mt   = blockIdx.x;
    const int nt   = blockIdx.y;

    // ---- per-thread load slots (fixed across the K loop) ----
    // A: 4 slots (2 subtiles x 128 rows x 8 x 16B = 2048 uint4 / 512 thr)
    int cbase[4], hh[4], ww[4];
    uint32_t dstA[4];
#pragma unroll
    for (int j = 0; j < 4; ++j) {
        int s = tid + j * 512;
        int t = s >> 10;            // M subtile 0/1
        int r = (s >> 3) & 127;     // row in subtile
        int u = s & 7;              // 16B unit
        int p = mt * 256 + t * 128 + r;
        int n = p / IMG;
        int rem = p - n * IMG;
        int h = rem / HW;
        int w = rem - h * HW;
        hh[j] = h; ww[j] = w;
        cbase[j] = ((n * HW + h) * HW + w) * CIN + u * 8;    // in halfs
        dstA[j]  = t * A_SUB + r * 128 + ((u ^ (r & 7)) << 4);
    }
    // B: 2 slots (128 rows x 8 x 16B = 1024 uint4 / 512 thr)
    int bsrc[2];
    uint32_t dstB[2];
#pragma unroll
    for (int j = 0; j < 2; ++j) {
        int s = tid + j * 512;
        int r = s >> 3;
        int u = s & 7;
        bsrc[j] = (nt * 128 + r) * KTOT + u * 8;             // in halfs
        dstB[j] = B_OFF + r * 128 + ((u ^ (r & 7)) << 4);
    }

    // ---- warp tiling ----
    const int wm = (wid & 3) * 64;
    const int wn = (wid >> 2) * 32;
    const int at = wm >> 7;
    const int am = wm & 127;

    float acc[4][4][4];
#pragma unroll
    for (int i = 0; i < 4; ++i)
#pragma unroll
        for (int j = 0; j < 4; ++j)
#pragma unroll
            for (int q = 0; q < 4; ++q) acc[i][j][q] = 0.f;

    auto issue_loads = [&](int it, int buf) {
        int tap = it >> 1;
        int chh = it & 1;
        int kh = tap / 3, kw = tap - kh * 3;
        const int doff = ((kh - 1) * HW + (kw - 1)) * CIN + chh * 64;  // halfs
        const uint32_t bb = smem_u + buf * BUF_BYTES;
#pragma unroll
        for (int j = 0; j < 4; ++j) {
            unsigned h2 = (unsigned)(hh[j] + kh - 1);
            unsigned w2 = (unsigned)(ww[j] + kw - 1);
            bool ok = (h2 < (unsigned)HW) && (w2 < (unsigned)HW);
            cp16(bb + dstA[j], g_xq + cbase[j] + doff, ok);
        }
        const int woff = tap * CIN + chh * 64;                          // halfs
#pragma unroll
        for (int j = 0; j < 2; ++j)
            cp16(bb + dstB[j], g_wbin + bsrc[j] + woff, true);
    };

    issue_loads(0, 0); CP_COMMIT();
    issue_loads(1, 1); CP_COMMIT();
    issue_loads(2, 2); CP_COMMIT();

    for (int it = 0; it < 18; ++it) {
        CP_WAIT2();                 // chunk `it` resident
        __syncthreads();            // all warps done with chunk it-1; its buffer free
        if (it + 3 < 18) issue_loads(it + 3, (it + 3) & 3);
        CP_COMMIT();

        const uint32_t bb    = smem_u + (it & 3) * BUF_BYTES;
        const uint32_t Abase = bb + at * A_SUB;
        const uint32_t Bbase = bb + B_OFF;
        const int arow = am + (lane & 15);
        const int brow = wn + (lane & 15);
        const int khi  = (lane >> 4) << 4;   // byte half select

#pragma unroll
        for (int ks = 0; ks < 4; ++ks) {
            const int kb = ks * 32 + khi;    // byte col
            uint32_t a[4][4];
#pragma unroll
            for (int mf = 0; mf < 4; ++mf) {
                int row = arow + mf * 16;
                uint32_t off = (uint32_t)(row * 128 + kb) ^ (uint32_t)((row & 7) << 4);
                ldsm4(a[mf], Abase + off);
            }
            uint32_t b[2][4];
#pragma unroll
            for (int q = 0; q < 2; ++q) {
                int row = brow + q * 16;
                uint32_t off = (uint32_t)(row * 128 + kb) ^ (uint32_t)((row & 7) << 4);
                ldsm4(b[q], Bbase + off);
            }
#pragma unroll
            for (int mf = 0; mf < 4; ++mf)
#pragma unroll
                for (int nb = 0; nb < 4; ++nb) {
                    int q = nb >> 1, jj = nb & 1;
                    mma_f16(acc[mf][nb], a[mf], b[q][jj], b[q][jj + 2]);
                }
        }
    }

    // ---- epilogue: registers -> gmem ----
    const int r0 = lane >> 2;
    const int c0 = (lane & 3) * 2;
#pragma unroll
    for (int mf = 0; mf < 4; ++mf) {
        int m = mt * 256 + wm + mf * 16 + r0;
#pragma unroll
        for (int nb = 0; nb < 4; ++nb) {
            int co = nt * 128 + wn + nb * 8 + c0;
            float* p0 = out + (size_t)m * COUT + co;
            float* p1 = out + (size_t)(m + 8) * COUT + co;
            *(float2*)p0 = make_float2(acc[mf][nb][0], acc[mf][nb][1]);
            *(float2*)p1 = make_float2(acc[mf][nb][2], acc[mf][nb][3]);
        }
    }
}

// ---------------- launch ----------------
extern "C" void kernel_launch(void* const* d_in, const int* in_sizes, int n_in,
                              void* d_out, int out_size) {
    const float* x = (const float*)d_in[0];
    const float* w = (const float*)d_in[1];
    float* out = (float*)d_out;

    cudaFuncSetAttribute(conv_kernel,
                         cudaFuncAttributeMaxDynamicSharedMemorySize, DYN_SMEM);

    binarize_kernel<<<(COUT * KTOT + 255) / 256, 256>>>(w);
    quant_kernel<<<(NPOS * CIN / 4 + 255) / 256, 256>>>((const float4*)x);
    conv_kernel<<<dim3(NPOS / 256, 2), 512, DYN_SMEM>>>(out);
}